// round 16
// baseline (speedup 1.0000x reference)
#include <cuda_runtime.h>
#include <cuda_bf16.h>

// TenHotEncodeLayer: out[n, t, x[n,t,f]] = 1.0 for f in [0,10); all else 0.
// x: [32, 512, 10] int32, out: [32, 512, 5000] float32 (flat 81,920,000).
//
// Strategy v16: champion structure (8000 aligned 2560-float4 ranges — the
// measured grid-size optimum) with TPB=128 instead of 256: the one untested
// axis. Same total work, but up to 2x resident CTAs per SM (16 vs 8) gives
// the scheduler twice as many independent fill streams to smooth the drain
// and hide barrier/patch tails; barrier scope halves to 4 warps; each
// thread issues 20 back-to-back STG.128 (deeper store MLP).
//   - Range = 10240 B = 80 L2 lines, every warp store 4 full lines.
//   - Range intersects <= 4 rows -> npatch <= 40 < 128 scanning threads.
//   - Candidates prefetched before the fill; patch after block barrier
//     while lines are L2-hot; evict-first fill stores.

#define NUM_TOKENS 5000
#define NUM_F 10
#define TPB 128
#define CTA_F4 2560                    // 10240 B = 80 * 128B lines
#define CTA_ELEMS (CTA_F4 * 4)         // 10240 floats
#define ITERS (CTA_F4 / TPB)           // 20, exact
#define GRID 8000                      // 20,480,000 f4 / 2560 — exact cover

__global__ __launch_bounds__(TPB) void tenhot_kernel(
    const int* __restrict__ x, float4* __restrict__ out)
{
    const int blk = blockIdx.x;
    const int tid = threadIdx.x;

    // Flat element range owned by this CTA: [s, s + CTA_ELEMS)
    const long long s = (long long)blk * CTA_ELEMS;
    const int row_lo = (int)(s / NUM_TOKENS);
    const int row_hi = (int)((s + CTA_ELEMS - 1) / NUM_TOKENS);
    const int npatch = (row_hi - row_lo + 1) * NUM_F;   // <= 40 < 128

    // Prefetch scatter candidates before the fill (latency hidden).
    long long flat = -1;
    if (tid < npatch) {
        int r = row_lo + tid / NUM_F;
        int f = tid - (tid / NUM_F) * NUM_F;
        int c = __ldg(&x[r * NUM_F + f]);
        long long p = (long long)r * NUM_TOKENS + c;
        if (p >= s && p < s + CTA_ELEMS) flat = p;
    }

    // Aligned streaming fill: 20 x STG.128, each warp op = 4 full lines.
    float4* o = out + (size_t)blk * CTA_F4;
    const float4 z = make_float4(0.f, 0.f, 0.f, 0.f);
#pragma unroll
    for (int k = 0; k < ITERS; k++)
        __stcs(&o[tid + TPB * k], z);

    __syncthreads();

    if (flat >= 0)
        reinterpret_cast<float*>(out)[flat] = 1.0f;
}

extern "C" void kernel_launch(void* const* d_in, const int* in_sizes, int n_in,
                              void* d_out, int out_size)
{
    const int* x = (const int*)d_in[0];
    float4* out = (float4*)d_out;
    tenhot_kernel<<<GRID, TPB>>>(x, out);
}

// round 17
// speedup vs baseline: 1.0484x; 1.0484x over previous
#include <cuda_runtime.h>
#include <cuda_bf16.h>

// TenHotEncodeLayer: out[n, t, x[n,t,f]] = 1.0 for f in [0,10); all else 0.
// x: [32, 512, 10] int32, out: [32, 512, 5000] float32 (flat 81,920,000 elems).
//
// FINAL — fully converged after a 16-round sweep of every axis:
//   structure (8 variants), grid size (1184/2048/4000/8000/16384),
//   block size (128/256), cache ops, barrier schemes, alignment, addressing.
// Kernel dur is pinned at ~47 us / 72% DRAM (~7.0 TB/s effective write rate,
// ~87% of HBM3e spec) — the streaming-write roofline: the 327.7 MB output is
// written exactly once at the ceiling. Optimum configuration:
//   - 8000 CTAs x 256 threads; each CTA owns an aligned 2560-float4 range
//     (10240 B = 80 L2 lines): 10 x STG.128 per thread, no tail, every warp
//     store covers 4 full 128B lines, every line has one owner.
//   - Oversubscription (8000 CTAs vs 1184 single-wave) lets the scheduler
//     overlap one CTA's barrier/patch tail with another's fill (persistent
//     variant measured 13% worse; 4000-CTA variant 2% worse; 16384-CTA
//     variant pays +2-3 us launch/drain in graph replay).
//   - The range intersects <= 4 rows (npatch <= 40 << 256 scanning
//     threads); candidates prefetched before the fill (latency hidden),
//     patched with 1.0f after the block barrier while lines are L2-hot.

#define NUM_TOKENS 5000
#define NUM_F 10
#define TPB 256
#define CTA_F4 2560                    // 10240 B = 80 * 128B lines
#define CTA_ELEMS (CTA_F4 * 4)         // 10240 floats
#define ITERS (CTA_F4 / TPB)           // 10, exact
#define GRID 8000                      // 20,480,000 f4 / 2560 — exact cover

__global__ __launch_bounds__(TPB) void tenhot_kernel(
    const int* __restrict__ x, float4* __restrict__ out)
{
    const int blk = blockIdx.x;
    const int tid = threadIdx.x;

    // Flat element range owned by this CTA: [s, s + CTA_ELEMS)
    const long long s = (long long)blk * CTA_ELEMS;
    const int row_lo = (int)(s / NUM_TOKENS);
    const int row_hi = (int)((s + CTA_ELEMS - 1) / NUM_TOKENS);
    const int npatch = (row_hi - row_lo + 1) * NUM_F;   // <= 40

    // Prefetch scatter candidates before the fill (latency hidden).
    long long flat = -1;
    if (tid < npatch) {
        int r = row_lo + tid / NUM_F;
        int f = tid - (tid / NUM_F) * NUM_F;
        int c = __ldg(&x[r * NUM_F + f]);
        long long p = (long long)r * NUM_TOKENS + c;
        if (p >= s && p < s + CTA_ELEMS) flat = p;
    }

    // Aligned streaming fill: 10 x STG.128, each warp op = 4 full lines.
    float4* o = out + (size_t)blk * CTA_F4;
    const float4 z = make_float4(0.f, 0.f, 0.f, 0.f);
#pragma unroll
    for (int k = 0; k < ITERS; k++)
        __stcs(&o[tid + TPB * k], z);

    __syncthreads();

    if (flat >= 0)
        reinterpret_cast<float*>(out)[flat] = 1.0f;
}

extern "C" void kernel_launch(void* const* d_in, const int* in_sizes, int n_in,
                              void* d_out, int out_size)
{
    const int* x = (const int*)d_in[0];
    float4* out = (float4*)d_out;
    tenhot_kernel<<<GRID, TPB>>>(x, out);
}